// round 6
// baseline (speedup 1.0000x reference)
#include <cuda_runtime.h>

// x: (4096, 8192) fp32, row-major. p = x[:, :4096], q = x[:, 4096:].
// out[:, :4096] = p
// out[:, 4096:] = weight[row] * selu(p) + q

#define SIZE    4096
#define HALF4   (SIZE / 4)          // 1024 float4 per half-row
#define ROW4    (2 * SIZE / 4)      // 2048 float4 per full x row
#define TOTAL4  (SIZE * HALF4)      // 4,194,304 float4-pairs

#define NBLOCKS 1184                // 148 SMs * 8 resident blocks = one wave
#define NTHREADS 256

__device__ __forceinline__ float selu_f(float v) {
    const float SCALE = 1.0507009873554804934193349852946f;
    const float ALPHA = 1.6732632423543772848170429916717f;
    float neg = SCALE * ALPHA * (__expf(fminf(v, 0.0f)) - 1.0f);
    float pos = SCALE * v;
    return v > 0.0f ? pos : neg;
}

__global__ __launch_bounds__(NTHREADS, 8) void selu_fuse_kernel(
    const float4* __restrict__ x,
    const float*  __restrict__ weight,
    float4*       __restrict__ out)
{
    const int stride = NBLOCKS * NTHREADS;     // 303104, compile-time
    int i = blockIdx.x * NTHREADS + threadIdx.x;

    #pragma unroll 2
    for (; i < TOTAL4; i += stride) {
        int row  = i >> 10;          // i / 1024
        int col4 = i & 1023;         // i % 1024

        long long off = (long long)row * ROW4 + col4;

        float4 p = x[off];
        float4 q = x[off + HALF4];
        float  w = __ldg(weight + row);

        float4 r;
        r.x = fmaf(w, selu_f(p.x), q.x);
        r.y = fmaf(w, selu_f(p.y), q.y);
        r.z = fmaf(w, selu_f(p.z), q.z);
        r.w = fmaf(w, selu_f(p.w), q.w);

        out[off]         = p;   // pass-through first half
        out[off + HALF4] = r;   // fused second half
    }
}

extern "C" void kernel_launch(void* const* d_in, const int* in_sizes, int n_in,
                              void* d_out, int out_size)
{
    const float4* x = (const float4*)d_in[0];
    const float*  w = (const float*)d_in[1];
    float4* out = (float4*)d_out;

    selu_fuse_kernel<<<NBLOCKS, NTHREADS>>>(x, w, out);
}

// round 8
// speedup vs baseline: 1.0726x; 1.0726x over previous
#include <cuda_runtime.h>

// x: (4096, 8192) fp32, row-major. p = x[:, :4096], q = x[:, 4096:].
// out[:, :4096] = p
// out[:, 4096:] = weight[row] * selu(p) + q
//
// Blackwell 256-bit global accesses: each thread handles one 8-float chunk of
// p and the matching chunk of q => 2 LDG.256 + 2 STG.256 per thread.

#define SIZE    4096
#define HALF8   (SIZE / 8)          // 512 float8 per half-row
#define ROWLEN  (2 * SIZE)          // 8192 floats per x row
#define TOTAL8  (SIZE * HALF8)      // 2,097,152 float8-pairs

__device__ __forceinline__ float selu_f(float v) {
    const float SCALE = 1.0507009873554804934193349852946f;
    const float ALPHA = 1.6732632423543772848170429916717f;
    float neg = SCALE * ALPHA * (__expf(fminf(v, 0.0f)) - 1.0f);
    float pos = SCALE * v;
    return v > 0.0f ? pos : neg;
}

__device__ __forceinline__ void ldg256(float r[8], const float* p) {
    asm volatile("ld.global.v8.f32 {%0,%1,%2,%3,%4,%5,%6,%7}, [%8];"
                 : "=f"(r[0]), "=f"(r[1]), "=f"(r[2]), "=f"(r[3]),
                   "=f"(r[4]), "=f"(r[5]), "=f"(r[6]), "=f"(r[7])
                 : "l"(p));
}

__device__ __forceinline__ void stg256(float* p, const float r[8]) {
    asm volatile("st.global.v8.f32 [%0], {%1,%2,%3,%4,%5,%6,%7,%8};"
                 :: "l"(p),
                    "f"(r[0]), "f"(r[1]), "f"(r[2]), "f"(r[3]),
                    "f"(r[4]), "f"(r[5]), "f"(r[6]), "f"(r[7])
                 : "memory");
}

__global__ __launch_bounds__(256) void selu_fuse_kernel(
    const float* __restrict__ x,
    const float* __restrict__ weight,
    float*       __restrict__ out)
{
    int i = blockIdx.x * blockDim.x + threadIdx.x;   // float8-pair index

    int row  = i >> 9;           // i / 512
    int col8 = i & 511;          // i % 512

    long long base = (long long)row * ROWLEN + col8 * 8;

    float p[8], q[8];
    ldg256(p, x + base);
    ldg256(q, x + base + SIZE);

    float w = __ldg(weight + row);

    float r[8];
    #pragma unroll
    for (int j = 0; j < 8; j++)
        r[j] = fmaf(w, selu_f(p[j]), q[j]);

    stg256(out + base,        p);
    stg256(out + base + SIZE, r);
}

extern "C" void kernel_launch(void* const* d_in, const int* in_sizes, int n_in,
                              void* d_out, int out_size)
{
    const float* x = (const float*)d_in[0];
    const float* w = (const float*)d_in[1];
    float* out = (float*)d_out;

    const int block = 256;
    const int grid  = TOTAL8 / block;   // 8192

    selu_fuse_kernel<<<grid, block>>>(x, w, out);
}

// round 9
// speedup vs baseline: 1.1294x; 1.0529x over previous
#include <cuda_runtime.h>

// x: (4096, 8192) fp32, row-major. p = x[:, :4096], q = x[:, 4096:].
// out[:, :4096] = p
// out[:, 4096:] = weight[row] * selu(p) + q
//
// R3 structure (best: 35.7us kernel) + evict-first policy on the read stream
// only. Loads are touch-once (stream through L2 evict-first); stores keep
// default writeback so dirty output lines linger in the 126MB L2 and flush
// outside the kernel's critical window.

#define SIZE   4096
#define HALF4  (SIZE / 4)          // 1024 float4 per half-row
#define ROWLEN (2 * SIZE)          // 8192 floats per x row

__device__ __forceinline__ float selu_f(float v) {
    const float SCALE = 1.0507009873554804934193349852946f;
    const float ALPHA = 1.6732632423543772848170429916717f;
    float neg = SCALE * ALPHA * (__expf(fminf(v, 0.0f)) - 1.0f);
    float pos = SCALE * v;
    return v > 0.0f ? pos : neg;
}

__global__ __launch_bounds__(256) void selu_fuse_kernel(
    const float4* __restrict__ x,
    const float*  __restrict__ weight,
    float4*       __restrict__ out)
{
    long long i = (long long)blockIdx.x * blockDim.x + threadIdx.x;

    int row  = (int)(i >> 10);          // i / 1024
    int col4 = (int)(i & 1023);         // i % 1024

    const float4* prow = x + (long long)row * (ROWLEN / 4);
    float4 p = __ldcs(prow + col4);             // streaming read
    float4 q = __ldcs(prow + col4 + HALF4);     // streaming read

    float w = __ldg(weight + row);

    float4 r;
    r.x = fmaf(w, selu_f(p.x), q.x);
    r.y = fmaf(w, selu_f(p.y), q.y);
    r.z = fmaf(w, selu_f(p.z), q.z);
    r.w = fmaf(w, selu_f(p.w), q.w);

    float4* orow = out + (long long)row * (ROWLEN / 4);
    orow[col4]         = p;   // default writeback store
    orow[col4 + HALF4] = r;   // default writeback store
}

extern "C" void kernel_launch(void* const* d_in, const int* in_sizes, int n_in,
                              void* d_out, int out_size)
{
    const float4* x = (const float4*)d_in[0];
    const float*  w = (const float*)d_in[1];
    float4* out = (float4*)d_out;

    const int total4 = SIZE * HALF4;        // 4,194,304 threads
    const int block = 256;
    const int grid  = total4 / block;       // 16384

    selu_fuse_kernel<<<grid, block>>>(x, w, out);
}